// round 14
// baseline (speedup 1.0000x reference)
#include <cuda_runtime.h>
#include <cuda_fp16.h>
#include <math.h>
#include <stdint.h>

#define Hdim 2048
#define Idim 4096
#define Edim 8
#define Tdim 2048
#define TK   4096   // T * K slots (always exact: every token picks 2 experts)

// ---------------- scratch (static device arrays; no allocations) ----------------
__device__ __half d_tn[(size_t)Tdim * Hdim];  // normalized tokens (fp16)
__device__ float  d_g[(size_t)TK * Idim];     // gate proj (fp32)
__device__ float  d_u[(size_t)TK * Idim];     // up proj (fp32)
__device__ __half d_h[(size_t)TK * Idim];     // w * silu(g)*u (fp16, weight folded)
__device__ float  d_part[(size_t)TK * Hdim];  // down partials per slot
__device__ int    d_rows[TK];
__device__ float  d_wgt[TK];
__device__ int    d_slot[Tdim * 2];
__device__ int    d_topi[Tdim * 2];
__device__ float  d_topw[Tdim * 2];
__device__ int    d_counts[Edim];
__device__ int    d_cursor[Edim];
__device__ int    d_offsets[Edim + 1];

// ---------------- helpers ----------------
__device__ __forceinline__ float warpsum(float v) {
#pragma unroll
    for (int o = 16; o > 0; o >>= 1) v += __shfl_down_sync(0xFFFFFFFFu, v, o);
    return v;
}
__device__ __forceinline__ uint32_t smem_u32(const void* p) {
    uint32_t a;
    asm("{ .reg .u64 t; cvta.to.shared.u64 t, %1; cvt.u32.u64 %0, t; }" : "=r"(a) : "l"(p));
    return a;
}
__device__ __forceinline__ void cp16(uint32_t dst, const void* src) {
    asm volatile("cp.async.cg.shared.global [%0], [%1], 16;" :: "r"(dst), "l"(src) : "memory");
}
__device__ __forceinline__ unsigned pack2h(float lo, float hi) {
    __half2 h = __floats2half2_rn(lo, hi);   // .x (lo) in low 16 bits
    return *reinterpret_cast<unsigned*>(&h);
}
__device__ __forceinline__ void mma_f16(float c[4], const unsigned a[4],
                                        unsigned b0, unsigned b1) {
    asm volatile(
        "mma.sync.aligned.m16n8k16.row.col.f32.f16.f16.f32 "
        "{%0,%1,%2,%3}, {%4,%5,%6,%7}, {%8,%9}, {%0,%1,%2,%3};"
        : "+f"(c[0]), "+f"(c[1]), "+f"(c[2]), "+f"(c[3])
        : "r"(a[0]), "r"(a[1]), "r"(a[2]), "r"(a[3]), "r"(b0), "r"(b1));
}
__device__ __forceinline__ void ldsm4(unsigned r[4], uint32_t addr) {
    asm volatile("ldmatrix.sync.aligned.m8n8.x4.shared.b16 {%0,%1,%2,%3}, [%4];"
                 : "=r"(r[0]), "=r"(r[1]), "=r"(r[2]), "=r"(r[3]) : "r"(addr));
}

// ---------------- init: counters only (out is fully overwritten by combine) ----------------
__global__ void init_kernel() {
    if (threadIdx.x < Edim) {
        d_counts[threadIdx.x] = 0;
        d_cursor[threadIdx.x] = 0;
    }
}

// ---------------- RMSNorm + router + top-2 ----------------
__global__ __launch_bounds__(256) void routing_kernel(const float* __restrict__ x,
                                                      const float* __restrict__ nw,
                                                      const float* __restrict__ rw) {
    int t = blockIdx.x, tid = threadIdx.x, lane = tid & 31, warp = tid >> 5;
    const float* xr = x + (size_t)t * Hdim;
    __shared__ float sred[8];
    __shared__ float slog[8][9];
    __shared__ float s_rms;

    float ss = 0.0f;
    for (int i = tid; i < Hdim; i += 256) { float v = xr[i]; ss += v * v; }
    ss = warpsum(ss);
    if (lane == 0) sred[warp] = ss;
    __syncthreads();
    if (tid == 0) {
        float tot = 0.0f;
        for (int w = 0; w < 8; w++) tot += sred[w];
        s_rms = rsqrtf(tot / (float)Hdim + 1e-6f);
    }
    __syncthreads();
    float rms = s_rms;

    float acc[8];
#pragma unroll
    for (int e = 0; e < 8; e++) acc[e] = 0.0f;
    for (int i = tid; i < Hdim; i += 256) {
        float tv = xr[i] * rms * nw[i];
        d_tn[(size_t)t * Hdim + i] = __float2half_rn(tv);
#pragma unroll
        for (int e = 0; e < 8; e++) acc[e] += tv * rw[i * Edim + e];
    }
#pragma unroll
    for (int e = 0; e < 8; e++) {
        float v = warpsum(acc[e]);
        if (lane == 0) slog[warp][e] = v;
    }
    __syncthreads();
    if (tid == 0) {
        float lg[8];
        for (int e = 0; e < 8; e++) {
            float s = 0.0f;
            for (int w = 0; w < 8; w++) s += slog[w][e];
            lg[e] = s;
        }
        float mx = lg[0];
        for (int e = 1; e < 8; e++) mx = fmaxf(mx, lg[e]);
        float af[8], sum = 0.0f;
        for (int e = 0; e < 8; e++) { af[e] = expf(lg[e] - mx); sum += af[e]; }
        float inv = 1.0f / sum;
        for (int e = 0; e < 8; e++) af[e] *= inv;
        int i1 = 0;
        for (int e = 1; e < 8; e++) if (af[e] > af[i1]) i1 = e;
        int i2 = (i1 == 0) ? 1 : 0;
        for (int e = 0; e < 8; e++) if (e != i1 && af[e] > af[i2]) i2 = e;
        float v1 = af[i1], v2 = af[i2], s2 = v1 + v2;
        d_topi[2 * t] = i1;  d_topi[2 * t + 1] = i2;
        d_topw[2 * t] = v1 / s2;  d_topw[2 * t + 1] = v2 / s2;
        atomicAdd(&d_counts[i1], 1);
        atomicAdd(&d_counts[i2], 1);
    }
}

__global__ void scan_kernel() {
    if (threadIdx.x == 0) {
        int o = 0;
        for (int e = 0; e < Edim; e++) { d_offsets[e] = o; o += d_counts[e]; }
        d_offsets[Edim] = o;
    }
}

__global__ void assign_kernel() {
    int t = blockIdx.x * blockDim.x + threadIdx.x;
    if (t >= Tdim) return;
    for (int k = 0; k < 2; k++) {
        int e = d_topi[2 * t + k];
        int p = d_offsets[e] + atomicAdd(&d_cursor[e], 1);
        d_rows[p] = t;
        d_wgt[p] = d_topw[2 * t + k];
        d_slot[2 * t + k] = p;
    }
}

// ---------------- grouped GEMM (R7 core), fp16 m16n8k16, 4-stage cp.async ----------------
// CTA tile 128x128, BK=32, 8 warps (2m x 4n), warp tile 64x32, 2 CTA/SM.
// A: fp16, 128 rows x 64B, granule-swizzled (g ^= (r>>1)&3), ldmatrix.x4.
// B: fp32 [k][n], pitch 528B, packed to fp16 in registers.
// mf-skip: fragments whose 16-row band lies beyond `valid` are skipped
// (warp-uniform predicate; full tiles unaffected).
// MODE 0: projection (A = gathered d_tn -> d_g/d_u per z&1). N=Idim, K=Hdim.
// MODE 1: down (A = d_h rows, plain store -> d_part by slot). N=Hdim, K=Idim.

#define BPH   528
#define ASTG  8192
#define STG   (ASTG + 32 * BPH)       // 25088
#define NSTG  4
#define SMEM_TOT (NSTG * STG + 1024)  // 101376 -> 2 CTAs/SM

template <int MODE>
__global__ __launch_bounds__(256, 2) void mma_gemm(const float* __restrict__ W0,
                                                   const float* __restrict__ W1) {
    constexpr int NDIM = (MODE == 1) ? Hdim : Idim;
    constexpr int KDIM = (MODE == 1) ? Idim : Hdim;
    constexpr int NK = KDIM / 32;

    const int zz = blockIdx.z;
    const int e = (MODE == 0) ? (zz >> 1) : zz;
    const int cnt = d_counts[e];
    const int m0 = blockIdx.x * 128;
    if (m0 >= cnt) return;
    const int base = d_offsets[e];
    const int n0 = blockIdx.y * 128;
    const int valid = cnt - m0;

    const float* W = (MODE == 0) ? ((zz & 1) ? W1 : W0) : W0;

    extern __shared__ char smem[];
    const uint32_t sb = smem_u32(smem);
    const int tid = threadIdx.x, wid = tid >> 5, lane = tid & 31;
    const int wm = wid & 1, wn = wid >> 1;
    const int qid = lane >> 2, kl = lane & 3;

    int* tokS = (int*)(smem + NSTG * STG);
    if (MODE == 0 && tid < 128) {
        int slot = base + m0 + min(tid, valid - 1);
        tokS[tid] = d_rows[slot];
    }
    __syncthreads();

    // ---- A staging: each thread copies 2 granules (rows r0, r0+64; k-group g) ----
    const int r0 = tid >> 2, gA = tid & 3;
    const __half* arow0;
    const __half* arow1;
    if (MODE == 0) {
        arow0 = d_tn + (size_t)tokS[min(r0, valid - 1)] * KDIM + gA * 8;
        arow1 = d_tn + (size_t)tokS[min(r0 + 64, valid - 1)] * KDIM + gA * 8;
    } else {
        arow0 = d_h + (size_t)(base + m0 + min(r0, valid - 1)) * KDIM + gA * 8;
        arow1 = d_h + (size_t)(base + m0 + min(r0 + 64, valid - 1)) * KDIM + gA * 8;
    }
    const uint32_t sw = (gA ^ ((r0 >> 1) & 3)) * 16;   // same for r0 and r0+64
    const uint32_t adst0 = r0 * 64 + sw;
    const uint32_t adst1 = (r0 + 64) * 64 + sw;

    const float* Wsrc = W + (size_t)e * KDIM * NDIM + n0 + lane * 4;

    auto load_stage = [&](int kc, int buf) {
        uint32_t ab = sb + buf * STG;
        const int k0 = kc * 32;
        cp16(ab + adst0, arow0 + k0);
        cp16(ab + adst1, arow1 + k0);
        uint32_t bb = ab + ASTG;
#pragma unroll
        for (int j = 0; j < 4; j++) {
            int kk = j * 8 + wid;
            cp16(bb + kk * BPH + lane * 16, Wsrc + (size_t)(k0 + kk) * NDIM);
        }
        asm volatile("cp.async.commit_group;" ::: "memory");
    };

    // ---- ldmatrix per-lane address pieces ----
    const int t8 = lane >> 3;
    const int gt = t8 >> 1;                        // k-granule within ks16
    const int rL = (t8 & 1) * 8 + (lane & 7);      // row within 16-row frag
    uint32_t r64[4], swm[4];
    bool mok[4];
#pragma unroll
    for (int mf = 0; mf < 4; mf++) {
        int r = wm * 64 + mf * 16 + rL;
        r64[mf] = r * 64;
        swm[mf] = (r >> 1) & 3;
        mok[mf] = (wm * 64 + mf * 16) < valid;     // warp-uniform fragment guard
    }

    float acc[4][4][4];
#pragma unroll
    for (int mf = 0; mf < 4; mf++)
#pragma unroll
        for (int nf = 0; nf < 4; nf++)
#pragma unroll
            for (int q = 0; q < 4; q++) acc[mf][nf][q] = 0.0f;

    load_stage(0, 0);
    load_stage(1, 1);
    load_stage(2, 2);

#pragma unroll 1
    for (int kc = 0; kc < NK; kc++) {
        if (kc < NK - 2)       asm volatile("cp.async.wait_group 2;" ::: "memory");
        else if (kc == NK - 2) asm volatile("cp.async.wait_group 1;" ::: "memory");
        else                   asm volatile("cp.async.wait_group 0;" ::: "memory");
        __syncthreads();
        if (kc + 3 < NK) load_stage(kc + 3, (kc + 3) & 3);

        const uint32_t Abase = sb + (kc & 3) * STG;
        const char* Bb = smem + (kc & 3) * STG + ASTG;
#pragma unroll
        for (int ks16 = 0; ks16 < 2; ks16++) {
            unsigned a[4][4];
#pragma unroll
            for (int mf = 0; mf < 4; mf++)
                if (mok[mf])
                    ldsm4(a[mf], Abase + r64[mf] + (((ks16 * 2 + gt) ^ swm[mf]) << 4));
            const int ksr = ks16 * 16;
#pragma unroll
            for (int nf = 0; nf < 4; nf++) {
                const char* p = Bb + (wn * 32 + nf * 8 + qid) * 4;
                float b00 = *(const float*)(p + (ksr + 2 * kl) * BPH);
                float b01 = *(const float*)(p + (ksr + 2 * kl + 1) * BPH);
                float b10 = *(const float*)(p + (ksr + 2 * kl + 8) * BPH);
                float b11 = *(const float*)(p + (ksr + 2 * kl + 9) * BPH);
                unsigned b0 = pack2h(b00, b01);
                unsigned b1 = pack2h(b10, b11);
#pragma unroll
                for (int mf = 0; mf < 4; mf++)
                    if (mok[mf])
                        mma_f16(acc[mf][nf], a[mf], b0, b1);
            }
        }
    }

    // ---------------- epilogue ----------------
#pragma unroll
    for (int mf = 0; mf < 4; mf++) {
#pragma unroll
        for (int half = 0; half < 2; half++) {
            int r = wm * 64 + mf * 16 + qid + half * 8;
            if (r >= valid) continue;
#pragma unroll
            for (int nf = 0; nf < 4; nf++) {
                int col = n0 + wn * 32 + nf * 8 + kl * 2;
                float v0 = acc[mf][nf][half * 2 + 0];
                float v1 = acc[mf][nf][half * 2 + 1];
                if (MODE == 0) {
                    float* Dst = (zz & 1) ? d_u : d_g;
                    *(float2*)(Dst + (size_t)(base + m0 + r) * Idim + col) =
                        make_float2(v0, v1);
                } else {
                    *(float2*)(d_part + (size_t)(base + m0 + r) * Hdim + col) =
                        make_float2(v0, v1);
                }
            }
        }
    }
}

// ---------------- h = w * silu(g) * u (weight folded; fp16 for the down GEMM) ----------------
__global__ void silu_kernel() {
    size_t n = (size_t)TK * Idim;
    for (size_t i = (size_t)blockIdx.x * blockDim.x + threadIdx.x; i < n;
         i += (size_t)gridDim.x * blockDim.x) {
        float g = d_g[i], u = d_u[i];
        float w = d_wgt[i >> 12];               // Idim == 4096 == 2^12
        float h = w * g / (1.0f + expf(-g)) * u;
        d_h[i] = __float2half_rn(h);
    }
}

// ---------------- combine: out[t] = part[slot0] + part[slot1] ----------------
__global__ __launch_bounds__(256) void combine_kernel(float* __restrict__ out) {
    int idx = blockIdx.x * blockDim.x + threadIdx.x;     // one float4 per thread
    int t = idx >> 9;                                     // Hdim/4 == 512
    int c4 = (idx & 511) << 2;
    int s0 = d_slot[2 * t], s1 = d_slot[2 * t + 1];
    float4 a = *(const float4*)(d_part + (size_t)s0 * Hdim + c4);
    float4 b = *(const float4*)(d_part + (size_t)s1 * Hdim + c4);
    float4 r = make_float4(a.x + b.x, a.y + b.y, a.z + b.z, a.w + b.w);
    *(float4*)(out + (size_t)t * Hdim + c4) = r;
}

// ---------------- launch ----------------
extern "C" void kernel_launch(void* const* d_in, const int* in_sizes, int n_in,
                              void* d_out, int out_size) {
    const float* x  = (const float*)d_in[0];
    const float* nw = (const float*)d_in[1];
    const float* rw = (const float*)d_in[2];
    const float* wg = (const float*)d_in[3];
    const float* wu = (const float*)d_in[4];
    const float* wd = (const float*)d_in[5];
    float* out = (float*)d_out;

    static bool attr_done = false;
    if (!attr_done) {
        cudaFuncSetAttribute(mma_gemm<0>, cudaFuncAttributeMaxDynamicSharedMemorySize, SMEM_TOT);
        cudaFuncSetAttribute(mma_gemm<1>, cudaFuncAttributeMaxDynamicSharedMemorySize, SMEM_TOT);
        attr_done = true;
    }

    init_kernel<<<1, 32>>>();
    routing_kernel<<<Tdim, 256>>>(x, nw, rw);
    scan_kernel<<<1, 32>>>();
    assign_kernel<<<Tdim / 256, 256>>>();

    // gate+up in one launch: z = expert*2 + {0:gate, 1:up}
    dim3 g1(TK / 128, Idim / 128, Edim * 2);   // 32 x 32 x 16, most x exit early
    mma_gemm<0><<<g1, 256, SMEM_TOT>>>(wg, wu);

    silu_kernel<<<2048, 256>>>();

    dim3 g2(TK / 128, Hdim / 128, Edim);       // 32 x 16 x 8
    mma_gemm<1><<<g2, 256, SMEM_TOT>>>(wd, nullptr);

    combine_kernel<<<(Tdim * Hdim / 4) / 256, 256>>>(out);
}

// round 16
// speedup vs baseline: 1.5893x; 1.5893x over previous
#include <cuda_runtime.h>
#include <cuda_fp16.h>
#include <math.h>
#include <stdint.h>

#define Hdim 2048
#define Idim 4096
#define Edim 8
#define Tdim 2048
#define TK   4096   // T * K slots (always exact: every token picks 2 experts)

// ---------------- scratch (static device arrays; no allocations) ----------------
__device__ __half d_tn[(size_t)Tdim * Hdim];  // normalized tokens (fp16)
__device__ float  d_g[(size_t)TK * Idim];     // gate proj (fp32)
__device__ float  d_u[(size_t)TK * Idim];     // up proj (fp32)
__device__ __half d_h[(size_t)TK * Idim];     // w * silu(g)*u (fp16, weight folded)
__device__ int    d_rows[TK];
__device__ float  d_wgt[TK];
__device__ int    d_topi[Tdim * 2];
__device__ float  d_topw[Tdim * 2];
__device__ int    d_counts[Edim];
__device__ int    d_cursor[Edim];
__device__ int    d_offsets[Edim + 1];

// ---------------- helpers ----------------
__device__ __forceinline__ float warpsum(float v) {
#pragma unroll
    for (int o = 16; o > 0; o >>= 1) v += __shfl_down_sync(0xFFFFFFFFu, v, o);
    return v;
}
__device__ __forceinline__ uint32_t smem_u32(const void* p) {
    uint32_t a;
    asm("{ .reg .u64 t; cvta.to.shared.u64 t, %1; cvt.u32.u64 %0, t; }" : "=r"(a) : "l"(p));
    return a;
}
__device__ __forceinline__ void cp16(uint32_t dst, const void* src) {
    asm volatile("cp.async.cg.shared.global [%0], [%1], 16;" :: "r"(dst), "l"(src) : "memory");
}
__device__ __forceinline__ unsigned pack2h(float lo, float hi) {
    __half2 h = __floats2half2_rn(lo, hi);   // .x (lo) in low 16 bits
    return *reinterpret_cast<unsigned*>(&h);
}
__device__ __forceinline__ void mma_f16(float c[4], const unsigned a[4],
                                        unsigned b0, unsigned b1) {
    asm volatile(
        "mma.sync.aligned.m16n8k16.row.col.f32.f16.f16.f32 "
        "{%0,%1,%2,%3}, {%4,%5,%6,%7}, {%8,%9}, {%0,%1,%2,%3};"
        : "+f"(c[0]), "+f"(c[1]), "+f"(c[2]), "+f"(c[3])
        : "r"(a[0]), "r"(a[1]), "r"(a[2]), "r"(a[3]), "r"(b0), "r"(b1));
}
__device__ __forceinline__ void ldsm4(unsigned r[4], uint32_t addr) {
    asm volatile("ldmatrix.sync.aligned.m8n8.x4.shared.b16 {%0,%1,%2,%3}, [%4];"
                 : "=r"(r[0]), "=r"(r[1]), "=r"(r[2]), "=r"(r[3]) : "r"(addr));
}

// ---------------- init ----------------
__global__ void init_kernel(float* __restrict__ out) {
    size_t n = (size_t)Tdim * Hdim;
    for (size_t i = (size_t)blockIdx.x * blockDim.x + threadIdx.x; i < n;
         i += (size_t)gridDim.x * blockDim.x)
        out[i] = 0.0f;
    if (blockIdx.x == 0 && threadIdx.x < Edim) {
        d_counts[threadIdx.x] = 0;
        d_cursor[threadIdx.x] = 0;
    }
}

// ---------------- RMSNorm + router + top-2 ----------------
__global__ __launch_bounds__(256) void routing_kernel(const float* __restrict__ x,
                                                      const float* __restrict__ nw,
                                                      const float* __restrict__ rw) {
    int t = blockIdx.x, tid = threadIdx.x, lane = tid & 31, warp = tid >> 5;
    const float* xr = x + (size_t)t * Hdim;
    __shared__ float sred[8];
    __shared__ float slog[8][9];
    __shared__ float s_rms;

    float ss = 0.0f;
    for (int i = tid; i < Hdim; i += 256) { float v = xr[i]; ss += v * v; }
    ss = warpsum(ss);
    if (lane == 0) sred[warp] = ss;
    __syncthreads();
    if (tid == 0) {
        float tot = 0.0f;
        for (int w = 0; w < 8; w++) tot += sred[w];
        s_rms = rsqrtf(tot / (float)Hdim + 1e-6f);
    }
    __syncthreads();
    float rms = s_rms;

    float acc[8];
#pragma unroll
    for (int e = 0; e < 8; e++) acc[e] = 0.0f;
    for (int i = tid; i < Hdim; i += 256) {
        float tv = xr[i] * rms * nw[i];
        d_tn[(size_t)t * Hdim + i] = __float2half_rn(tv);
#pragma unroll
        for (int e = 0; e < 8; e++) acc[e] += tv * rw[i * Edim + e];
    }
#pragma unroll
    for (int e = 0; e < 8; e++) {
        float v = warpsum(acc[e]);
        if (lane == 0) slog[warp][e] = v;
    }
    __syncthreads();
    if (tid == 0) {
        float lg[8];
        for (int e = 0; e < 8; e++) {
            float s = 0.0f;
            for (int w = 0; w < 8; w++) s += slog[w][e];
            lg[e] = s;
        }
        float mx = lg[0];
        for (int e = 1; e < 8; e++) mx = fmaxf(mx, lg[e]);
        float af[8], sum = 0.0f;
        for (int e = 0; e < 8; e++) { af[e] = expf(lg[e] - mx); sum += af[e]; }
        float inv = 1.0f / sum;
        for (int e = 0; e < 8; e++) af[e] *= inv;
        int i1 = 0;
        for (int e = 1; e < 8; e++) if (af[e] > af[i1]) i1 = e;
        int i2 = (i1 == 0) ? 1 : 0;
        for (int e = 0; e < 8; e++) if (e != i1 && af[e] > af[i2]) i2 = e;
        float v1 = af[i1], v2 = af[i2], s2 = v1 + v2;
        d_topi[2 * t] = i1;  d_topi[2 * t + 1] = i2;
        d_topw[2 * t] = v1 / s2;  d_topw[2 * t + 1] = v2 / s2;
        atomicAdd(&d_counts[i1], 1);
        atomicAdd(&d_counts[i2], 1);
    }
}

__global__ void scan_kernel() {
    if (threadIdx.x == 0) {
        int o = 0;
        for (int e = 0; e < Edim; e++) { d_offsets[e] = o; o += d_counts[e]; }
        d_offsets[Edim] = o;
    }
}

__global__ void assign_kernel() {
    int t = blockIdx.x * blockDim.x + threadIdx.x;
    if (t >= Tdim) return;
    for (int k = 0; k < 2; k++) {
        int e = d_topi[2 * t + k];
        int p = d_offsets[e] + atomicAdd(&d_cursor[e], 1);
        d_rows[p] = t;
        d_wgt[p] = d_topw[2 * t + k];
    }
}

// ---------------- grouped GEMM (R7 core, unmodified), fp16 m16n8k16 ----------------
// CTA tile 128x128, BK=32, 8 warps (2m x 4n), warp tile 64x32, 2 CTA/SM.
// A in SMEM: fp16, 128 rows x 64B, granule-swizzled (g ^= (r>>1)&3), ldmatrix.x4.
// B in SMEM: fp32 [k][n], pitch 528B, packed to fp16 in registers.
// MODE 0: projection (A = gathered d_tn -> d_g/d_u per z&1). N=Idim, K=Hdim.
// MODE 1: down (A = d_h rows [weight pre-folded], atomicAdd -> out). N=Hdim, K=Idim.

#define BPH   528
#define ASTG  8192
#define STG   (ASTG + 32 * BPH)       // 25088
#define NSTG  4
#define SMEM_TOT (NSTG * STG + 1024)  // 101376 -> 2 CTAs/SM

template <int MODE>
__global__ __launch_bounds__(256, 2) void mma_gemm(const float* __restrict__ W0,
                                                   const float* __restrict__ W1,
                                                   float* __restrict__ Out) {
    constexpr int NDIM = (MODE == 1) ? Hdim : Idim;
    constexpr int KDIM = (MODE == 1) ? Idim : Hdim;
    constexpr int NK = KDIM / 32;

    const int zz = blockIdx.z;
    const int e = (MODE == 0) ? (zz >> 1) : zz;
    const int cnt = d_counts[e];
    const int m0 = blockIdx.x * 128;
    if (m0 >= cnt) return;
    const int base = d_offsets[e];
    const int n0 = blockIdx.y * 128;
    const int valid = cnt - m0;

    const float* W = (MODE == 0) ? ((zz & 1) ? W1 : W0) : W0;
    float* Dst = (MODE == 0) ? (((zz & 1) ? d_u : d_g)) : Out;

    extern __shared__ char smem[];
    const uint32_t sb = smem_u32(smem);
    const int tid = threadIdx.x, wid = tid >> 5, lane = tid & 31;
    const int wm = wid & 1, wn = wid >> 1;
    const int qid = lane >> 2, kl = lane & 3;

    int* tokS = (int*)(smem + NSTG * STG);
    if (tid < 128) {
        int slot = base + m0 + min(tid, valid - 1);
        tokS[tid] = d_rows[slot];
    }
    __syncthreads();

    // ---- A staging: each thread copies 2 granules (rows r0, r0+64; k-group g) ----
    const int r0 = tid >> 2, gA = tid & 3;
    const __half* arow0;
    const __half* arow1;
    if (MODE == 0) {
        arow0 = d_tn + (size_t)tokS[min(r0, valid - 1)] * KDIM + gA * 8;
        arow1 = d_tn + (size_t)tokS[min(r0 + 64, valid - 1)] * KDIM + gA * 8;
    } else {
        arow0 = d_h + (size_t)(base + m0 + min(r0, valid - 1)) * KDIM + gA * 8;
        arow1 = d_h + (size_t)(base + m0 + min(r0 + 64, valid - 1)) * KDIM + gA * 8;
    }
    const uint32_t sw = (gA ^ ((r0 >> 1) & 3)) * 16;   // same for r0 and r0+64
    const uint32_t adst0 = r0 * 64 + sw;
    const uint32_t adst1 = (r0 + 64) * 64 + sw;

    const float* Wsrc = W + (size_t)e * KDIM * NDIM + n0 + lane * 4;

    auto load_stage = [&](int kc, int buf) {
        uint32_t ab = sb + buf * STG;
        const int k0 = kc * 32;
        cp16(ab + adst0, arow0 + k0);
        cp16(ab + adst1, arow1 + k0);
        uint32_t bb = ab + ASTG;
#pragma unroll
        for (int j = 0; j < 4; j++) {
            int kk = j * 8 + wid;
            cp16(bb + kk * BPH + lane * 16, Wsrc + (size_t)(k0 + kk) * NDIM);
        }
        asm volatile("cp.async.commit_group;" ::: "memory");
    };

    // ---- ldmatrix per-lane address pieces ----
    const int t8 = lane >> 3;
    const int gt = t8 >> 1;                        // k-granule within ks16
    const int rL = (t8 & 1) * 8 + (lane & 7);      // row within 16-row frag
    uint32_t r64[4], swm[4];
#pragma unroll
    for (int mf = 0; mf < 4; mf++) {
        int r = wm * 64 + mf * 16 + rL;
        r64[mf] = r * 64;
        swm[mf] = (r >> 1) & 3;
    }

    float acc[4][4][4];
#pragma unroll
    for (int mf = 0; mf < 4; mf++)
#pragma unroll
        for (int nf = 0; nf < 4; nf++)
#pragma unroll
            for (int q = 0; q < 4; q++) acc[mf][nf][q] = 0.0f;

    load_stage(0, 0);
    load_stage(1, 1);
    load_stage(2, 2);

#pragma unroll 1
    for (int kc = 0; kc < NK; kc++) {
        if (kc < NK - 2)       asm volatile("cp.async.wait_group 2;" ::: "memory");
        else if (kc == NK - 2) asm volatile("cp.async.wait_group 1;" ::: "memory");
        else                   asm volatile("cp.async.wait_group 0;" ::: "memory");
        __syncthreads();
        if (kc + 3 < NK) load_stage(kc + 3, (kc + 3) & 3);

        const uint32_t Abase = sb + (kc & 3) * STG;
        const char* Bb = smem + (kc & 3) * STG + ASTG;
#pragma unroll
        for (int ks16 = 0; ks16 < 2; ks16++) {
            unsigned a[4][4];
#pragma unroll
            for (int mf = 0; mf < 4; mf++)
                ldsm4(a[mf], Abase + r64[mf] + (((ks16 * 2 + gt) ^ swm[mf]) << 4));
            const int ksr = ks16 * 16;
#pragma unroll
            for (int nf = 0; nf < 4; nf++) {
                const char* p = Bb + (wn * 32 + nf * 8 + qid) * 4;
                float b00 = *(const float*)(p + (ksr + 2 * kl) * BPH);
                float b01 = *(const float*)(p + (ksr + 2 * kl + 1) * BPH);
                float b10 = *(const float*)(p + (ksr + 2 * kl + 8) * BPH);
                float b11 = *(const float*)(p + (ksr + 2 * kl + 9) * BPH);
                unsigned b0 = pack2h(b00, b01);
                unsigned b1 = pack2h(b10, b11);
#pragma unroll
                for (int mf = 0; mf < 4; mf++)
                    mma_f16(acc[mf][nf], a[mf], b0, b1);
            }
        }
    }

    // ---------------- epilogue ----------------
#pragma unroll
    for (int mf = 0; mf < 4; mf++) {
#pragma unroll
        for (int half = 0; half < 2; half++) {
            int r = wm * 64 + mf * 16 + qid + half * 8;
            if (r >= valid) continue;
#pragma unroll
            for (int nf = 0; nf < 4; nf++) {
                int col = n0 + wn * 32 + nf * 8 + kl * 2;
                float v0 = acc[mf][nf][half * 2 + 0];
                float v1 = acc[mf][nf][half * 2 + 1];
                if (MODE == 0) {
                    *(float2*)(Dst + (size_t)(base + m0 + r) * Idim + col) =
                        make_float2(v0, v1);
                } else {
                    // combine weight already folded into d_h
                    int tok = tokS[r];
                    float* dst = Dst + (size_t)tok * Hdim + col;
                    atomicAdd(dst + 0, v0);
                    atomicAdd(dst + 1, v1);
                }
            }
        }
    }
}

// ---------------- h = w * silu(g) * u (vectorized; weight folded) ----------------
__global__ __launch_bounds__(256) void silu_kernel() {
    const float4* g4 = (const float4*)d_g;
    const float4* u4 = (const float4*)d_u;
    size_t n4 = (size_t)TK * Idim / 4;
    for (size_t i = (size_t)blockIdx.x * blockDim.x + threadIdx.x; i < n4;
         i += (size_t)gridDim.x * blockDim.x) {
        float4 g = g4[i];
        float4 u = u4[i];
        float w = d_wgt[i >> 10];              // (i*4) >> 12 == i >> 10 (Idim = 4096)
        float h0 = w * g.x / (1.0f + expf(-g.x)) * u.x;
        float h1 = w * g.y / (1.0f + expf(-g.y)) * u.y;
        float h2 = w * g.z / (1.0f + expf(-g.z)) * u.z;
        float h3 = w * g.w / (1.0f + expf(-g.w)) * u.w;
        __half2 lo = __floats2half2_rn(h0, h1);
        __half2 hi = __floats2half2_rn(h2, h3);
        *(uint2*)(d_h + i * 4) = make_uint2(*(unsigned*)&lo, *(unsigned*)&hi);
    }
}

// ---------------- launch ----------------
extern "C" void kernel_launch(void* const* d_in, const int* in_sizes, int n_in,
                              void* d_out, int out_size) {
    const float* x  = (const float*)d_in[0];
    const float* nw = (const float*)d_in[1];
    const float* rw = (const float*)d_in[2];
    const float* wg = (const float*)d_in[3];
    const float* wu = (const float*)d_in[4];
    const float* wd = (const float*)d_in[5];
    float* out = (float*)d_out;

    static bool attr_done = false;
    if (!attr_done) {
        cudaFuncSetAttribute(mma_gemm<0>, cudaFuncAttributeMaxDynamicSharedMemorySize, SMEM_TOT);
        cudaFuncSetAttribute(mma_gemm<1>, cudaFuncAttributeMaxDynamicSharedMemorySize, SMEM_TOT);
        attr_done = true;
    }

    init_kernel<<<512, 256>>>(out);
    routing_kernel<<<Tdim, 256>>>(x, nw, rw);
    scan_kernel<<<1, 32>>>();
    assign_kernel<<<Tdim / 256, 256>>>();

    // gate+up in one launch: z = expert*2 + {0:gate, 1:up}
    dim3 g1(TK / 128, Idim / 128, Edim * 2);   // 32 x 32 x 16, most x exit early
    mma_gemm<0><<<g1, 256, SMEM_TOT>>>(wg, wu, nullptr);

    silu_kernel<<<1024, 256>>>();

    dim3 g2(TK / 128, Hdim / 128, Edim);       // 32 x 16 x 8
    mma_gemm<1><<<g2, 256, SMEM_TOT>>>(wd, nullptr, out);
}